// round 11
// baseline (speedup 1.0000x reference)
#include <cuda_runtime.h>
#include <cuda_bf16.h>
#include <cstdint>

// TransposeTDLayer via tf32 mma.sync + cp.async, K=32-chunk double buffer,
// 4 CTAs/SM, TWO output positions per CTA (grid 515 -> exactly one wave).
// y[b,p,o] = bias[p,o] + sum_{(k,l):k+2l=p} sum_ci W[k,l,o,ci] * x[b,l,ci]
// Positions 2m and 2m+1 share (j0, nblk) and the same X rows; one seamless
// cp.async chunk pipeline covers both, with pos0's epilogue overlapping
// pos1's loads. tf32 rounding via integer +0x1000 (validated bit-exact vs
// cvt.rna.tf32 in round 10).

#define BATCH 64
#define LIN   512
#define CIN   128
#define COUT  128
#define OUTP  1030

// chunk row stride: 32 fp32 + 4 pad = 36 words = 144 B (36 % 32 == 4)
#define RSTRIDE 144
#define A_OFF   0
#define A_BYTES (128 * RSTRIDE)            // 18432
#define B_OFF   A_BYTES
#define B_BYTES (64 * RSTRIDE)             // 9216
#define BUF_BYTES (A_BYTES + B_BYTES)      // 27648
#define SMEM_TOTAL (2 * BUF_BYTES)         // 55296/CTA -> 4 CTAs/SM

static __device__ __forceinline__ uint32_t smem_u32(const void* p) {
    uint32_t a;
    asm("{ .reg .u64 t; cvta.to.shared.u64 t, %1; cvt.u32.u64 %0, t; }"
        : "=r"(a) : "l"(p));
    return a;
}

static __device__ __forceinline__ void mma_tf32(
    float* c, const uint32_t* a, const uint32_t* b)
{
    asm volatile(
        "mma.sync.aligned.m16n8k8.row.col.f32.tf32.tf32.f32 "
        "{%0,%1,%2,%3}, {%4,%5,%6,%7}, {%8,%9}, {%0,%1,%2,%3};"
        : "+f"(c[0]), "+f"(c[1]), "+f"(c[2]), "+f"(c[3])
        : "r"(a[0]), "r"(a[1]), "r"(a[2]), "r"(a[3]), "r"(b[0]), "r"(b[1]));
}

static __device__ __forceinline__ void ldsm_x4(uint32_t* r, uint32_t addr) {
    asm volatile("ldmatrix.sync.aligned.m8n8.x4.shared.b16 {%0,%1,%2,%3}, [%4];"
                 : "=r"(r[0]), "=r"(r[1]), "=r"(r[2]), "=r"(r[3]) : "r"(addr));
}

// tf32 round-to-nearest via +half-ulp; tensor core truncates low 13 bits.
static __device__ __forceinline__ uint32_t round_tf32(uint32_t v) {
    return v + 0x1000u;
}

static __device__ __forceinline__ void cpasync16(uint32_t dst, const void* src) {
    asm volatile("cp.async.cg.shared.global [%0], [%1], 16;"
                 :: "r"(dst), "l"(src) : "memory");
}
#define CP_COMMIT() asm volatile("cp.async.commit_group;" ::: "memory")
#define CP_WAIT1()  asm volatile("cp.async.wait_group 1;" ::: "memory")

__global__ void __launch_bounds__(256, 4)
tdconv_tf32p2_kernel(const float* __restrict__ x,
                     const float* __restrict__ w,
                     const float* __restrict__ bias,
                     float* __restrict__ y)
{
    extern __shared__ char smem[];
    const uint32_t sbase = smem_u32(smem);

    const int tid  = threadIdx.x;
    const int wid  = tid >> 5;
    const int lane = tid & 31;

    const int mrow = (wid >> 1) * 32;   // cout base (0,32,64,96)
    const int ncol = (wid & 1) * 32;    // batch base (0,32)

    // this CTA handles positions p0 = 2m and p1 = 2m+1 (identical j-range)
    const int m = blockIdx.x;
    int j0 = m - (LIN - 1); if (j0 < 0) j0 = 0;
    int j1 = m < 3 ? m : 3;
    const int nblk = j1 - j0 + 1;
    const int n0   = 4 * nblk;          // chunks for pos0 (K=32 quarters)
    const int ntot = 2 * n0;            // pos0 then pos1

    // hoisted per-thread cp.async decomposition
    const int a_row = tid >> 3;                 // 0..31
    const int a_seg = (tid & 7) * 4;            // fp32 offset of 16B segment
    const uint32_t a_soff = (uint32_t)a_row * RSTRIDE + (uint32_t)(tid & 7) * 16;

    // issue cp.async for global chunk c into buf[c&1]
    auto issue_chunk = [&](int c) {
        if (c < ntot) {
            int cc = c, par = 0;
            if (cc >= n0) { cc -= n0; par = 1; }
            const int j = j0 + (cc >> 2);
            const int l = m - j;
            const int k = par + 2 * j;
            const int kh = (cc & 3) * 32;
            const float* __restrict__ wp =
                w + (size_t)(k * LIN + l) * (COUT * CIN) + kh + (size_t)a_row * CIN + a_seg;
            const float* __restrict__ xp =
                x + (size_t)l * CIN + kh + (size_t)a_row * (LIN * CIN) + a_seg;
            const uint32_t buf = sbase + (uint32_t)(c & 1) * BUF_BYTES;
            #pragma unroll
            for (int it = 0; it < 4; it++)
                cpasync16(buf + A_OFF + a_soff + (uint32_t)it * (32 * RSTRIDE),
                          wp + (size_t)it * (32 * CIN));
            #pragma unroll
            for (int it = 0; it < 2; it++)
                cpasync16(buf + B_OFF + a_soff + (uint32_t)it * (32 * RSTRIDE),
                          xp + (size_t)it * (32 * LIN * CIN));
        }
        CP_COMMIT();   // uniform group counting
    };

    // ldmatrix lane byte-offsets (within chunk)
    const uint32_t a_loff = A_OFF
        + (uint32_t)(mrow + (lane & 7) + ((lane >> 3) & 1) * 8) * RSTRIDE
        + (uint32_t)(lane >> 4) * 16;
    const uint32_t b_loff = B_OFF
        + (uint32_t)(ncol + (lane & 7) + (lane >> 4) * 8) * RSTRIDE
        + (uint32_t)((lane >> 3) & 1) * 16;

    const int g = lane >> 2;
    const int t = lane & 3;

    float acc[2][4][4];
    // init acc with bias for position p
    auto init_acc = [&](int p) {
        #pragma unroll
        for (int mi = 0; mi < 2; mi++) {
            const float b_g  = bias[p * COUT + mrow + mi * 16 + g];
            const float b_g8 = bias[p * COUT + mrow + mi * 16 + g + 8];
            #pragma unroll
            for (int ni = 0; ni < 4; ni++) {
                acc[mi][ni][0] = b_g;  acc[mi][ni][1] = b_g;
                acc[mi][ni][2] = b_g8; acc[mi][ni][3] = b_g8;
            }
        }
    };
    // write acc to y for position p (per-thread registers only; no sync needed)
    auto epilogue = [&](int p) {
        #pragma unroll
        for (int mi = 0; mi < 2; mi++) {
            const int o0 = mrow + mi * 16 + g;
            const int o8 = o0 + 8;
            #pragma unroll
            for (int ni = 0; ni < 4; ni++) {
                const int b0 = ncol + ni * 8 + 2 * t;
                float* y0 = y + ((size_t)b0 * OUTP + p) * COUT;
                float* y1 = y0 + (size_t)OUTP * COUT;
                y0[o0] = acc[mi][ni][0];
                y1[o0] = acc[mi][ni][1];
                y0[o8] = acc[mi][ni][2];
                y1[o8] = acc[mi][ni][3];
            }
        }
    };

    init_acc(2 * m);
    issue_chunk(0);
    issue_chunk(1);

    for (int c = 0; c < ntot; c++) {
        CP_WAIT1();
        __syncthreads();

        const uint32_t buf = sbase + (uint32_t)(c & 1) * BUF_BYTES;
        const uint32_t ab = buf + a_loff;
        const uint32_t bb = buf + b_loff;

        #pragma unroll
        for (int ks = 0; ks < 4; ks++) {           // 4 k8-steps over K=32
            const uint32_t koff = (uint32_t)ks * 32;
            uint32_t a[2][4], b[2][4];
            #pragma unroll
            for (int mi = 0; mi < 2; mi++)
                ldsm_x4(a[mi], ab + (uint32_t)mi * (16 * RSTRIDE) + koff);
            #pragma unroll
            for (int pr = 0; pr < 2; pr++)
                ldsm_x4(b[pr], bb + (uint32_t)pr * (16 * RSTRIDE) + koff);

            #pragma unroll
            for (int mi = 0; mi < 2; mi++)
                #pragma unroll
                for (int q = 0; q < 4; q++) a[mi][q] = round_tf32(a[mi][q]);
            #pragma unroll
            for (int pr = 0; pr < 2; pr++)
                #pragma unroll
                for (int q = 0; q < 4; q++) b[pr][q] = round_tf32(b[pr][q]);

            #pragma unroll
            for (int mi = 0; mi < 2; mi++)
                #pragma unroll
                for (int ni = 0; ni < 4; ni++)
                    mma_tf32(acc[mi][ni], a[mi], &b[ni >> 1][(ni & 1) * 2]);
        }

        // position boundary: drain pos0's acc (register-only), start pos1's
        if (c == n0 - 1) {
            epilogue(2 * m);
            init_acc(2 * m + 1);
        }

        __syncthreads();          // all warps done reading buf[c&1]
        issue_chunk(c + 2);       // refill (commits even when exhausted)
    }

    epilogue(2 * m + 1);
}

extern "C" void kernel_launch(void* const* d_in, const int* in_sizes, int n_in,
                              void* d_out, int out_size)
{
    const float* x    = (const float*)d_in[0];  // (64,512,128)
    const float* w    = (const float*)d_in[1];  // (8,512,128,128)
    const float* bias = (const float*)d_in[2];  // (1030,128)
    float* y = (float*)d_out;                   // (64,1030,128)

    static bool configured = false;
    if (!configured) {
        cudaFuncSetAttribute(tdconv_tf32p2_kernel,
                             cudaFuncAttributeMaxDynamicSharedMemorySize, SMEM_TOTAL);
        configured = true;
    }
    tdconv_tf32p2_kernel<<<OUTP / 2, 256, SMEM_TOTAL>>>(x, w, bias, y);
}